// round 1
// baseline (speedup 1.0000x reference)
#include <cuda_runtime.h>
#include <math.h>

#define T_SAMPLES 8388608
#define NFRAMES   16381
#define NBINS     84
#define FBINS     1025
#define FFTLEN    2048
#define HOP       512

// main kernel tiling
#define FT   64     // frames per block (32 lanes x 2 frames/thread)
#define KT   28     // bins per block (7 warps x 4 bins)
#define ROWS 67     // FT + 3 (frames overlap 4x at hop 512)
#define RPAD 516    // 512 + 4 pad: stride % 32 == 4 -> conflict-free LDS128
#define CH   128    // n-chunk staged in smem

#define SMEM_FLOATS (ROWS*RPAD + 2*KT*CH)
#define SMEM_BYTES  (SMEM_FLOATS * 4)

typedef unsigned long long ull;

// Combined CQT kernels: A = kr@wcos - ki@wsin, B = kr@wsin + ki@wcos
__device__ float g_A[NBINS * FFTLEN];
__device__ float g_B[NBINS * FFTLEN];

__device__ __forceinline__ ull ffma2(ull a, ull b, ull c) {
    ull d;
    asm("fma.rn.f32x2 %0, %1, %2, %3;" : "=l"(d) : "l"(a), "l"(b), "l"(c));
    return d;
}

#define LDSV2(lo, hi, addr) \
    asm volatile("ld.shared.v2.u64 {%0, %1}, [%2];" : "=l"(lo), "=l"(hi) : "r"(addr))

__device__ __forceinline__ float hsum2(ull v) {
    union { ull u; float2 f; } c; c.u = v;
    return c.f.x + c.f.y;
}

// ---------------------------------------------------------------------------
// Precompute A,B [84,2048] = combine(kr,ki [84,1025] ; wcos,wsin [1025,2048])
// Block: 256 threads = 4 k-slots x 64 n; each thread computes 3 bins x 1 n.
// kr/ki staged in smem per 64-b chunk (uniform broadcast reads).
// ---------------------------------------------------------------------------
__global__ void __launch_bounds__(256) cqt_precomp(const float* __restrict__ wcos,
                                                   const float* __restrict__ wsin,
                                                   const float* __restrict__ kr,
                                                   const float* __restrict__ ki) {
    __shared__ float skr[12 * 64];
    __shared__ float ski[12 * 64];
    const int tid = threadIdx.x;
    const int n   = blockIdx.x * 64 + (tid & 63);
    const int ks  = tid >> 6;               // 0..3
    const int kb  = blockIdx.y * 12;        // 7 blocks -> 84 bins

    float aA[3] = {0.f, 0.f, 0.f};
    float aB[3] = {0.f, 0.f, 0.f};

    for (int bc = 0; bc < FBINS; bc += 64) {
        const int blen = min(64, FBINS - bc);
        __syncthreads();
        for (int i = tid; i < 12 * 64; i += 256) {
            const int kk = i >> 6, bb = i & 63;
            float vr = 0.f, vi = 0.f;
            if (bb < blen) {
                vr = kr[(kb + kk) * FBINS + bc + bb];
                vi = ki[(kb + kk) * FBINS + bc + bb];
            }
            skr[i] = vr; ski[i] = vi;
        }
        __syncthreads();
        #pragma unroll 4
        for (int bb = 0; bb < blen; bb++) {
            const int b = bc + bb;
            const float wc = wcos[b * FFTLEN + n];
            const float ws = wsin[b * FFTLEN + n];
            #pragma unroll
            for (int i = 0; i < 3; i++) {
                const int kk = ks + 4 * i;
                const float vr = skr[kk * 64 + bb];
                const float vi = ski[kk * 64 + bb];
                aA[i] = fmaf(vr, wc, aA[i]);
                aA[i] = fmaf(-vi, ws, aA[i]);
                aB[i] = fmaf(vr, ws, aB[i]);
                aB[i] = fmaf(vi, wc, aB[i]);
            }
        }
    }
    #pragma unroll
    for (int i = 0; i < 3; i++) {
        const int k = kb + ks + 4 * i;
        g_A[k * FFTLEN + n] = aA[i];
        g_B[k * FFTLEN + n] = aB[i];
    }
}

// ---------------------------------------------------------------------------
// Main kernel: cqt[k,f] = sqrt((A[k]·frame_f)^2 + (B[k]·frame_f)^2)
// frame_f[n] = x[512*f + n]. Block = 28 bins x 64 frames, 224 threads.
// x segment cached in smem (rows of 512 samples, pad 516); A/B chunk staged
// in smem, read as warp-uniform broadcast LDS128. Accumulation in packed
// f32x2 (fma.rn.f32x2) over n-pairs.
// ---------------------------------------------------------------------------
__global__ void __launch_bounds__(224, 1) cqt_main(const float* __restrict__ x,
                                                   float* __restrict__ out) {
    extern __shared__ float smem[];
    float* xs = smem;                    // ROWS * RPAD
    float* sA = smem + ROWS * RPAD;      // KT * CH
    float* sB = sA + KT * CH;

    const int tid   = threadIdx.x;
    const int lane  = tid & 31;
    const int warp  = tid >> 5;          // 0..6
    const int bf    = blockIdx.x;        // 0..255 frame tile
    const int bk    = blockIdx.y;        // 0..2 bin tile
    const int kbase = bk * KT;

    // ---- load x segment (ROWS*512 samples, zero-fill OOB) ----
    {
        const int base4 = bf * (FT * HOP / 4);
        const float4* x4 = (const float4*)x;
        for (int i4 = tid; i4 < ROWS * (HOP / 4); i4 += 224) {
            const int m  = i4 >> 7;      // /128
            const int r4 = i4 & 127;
            const int g4 = base4 + i4;
            float4 v = make_float4(0.f, 0.f, 0.f, 0.f);
            if (g4 < T_SAMPLES / 4) v = x4[g4];
            *(float4*)(xs + m * RPAD + r4 * 4) = v;
        }
    }

    ull aR0[4], aR1[4], aI0[4], aI1[4];
    #pragma unroll
    for (int q = 0; q < 4; q++) { aR0[q] = aR1[q] = aI0[q] = aI1[q] = 0ULL; }

    const unsigned xs_u = (unsigned)__cvta_generic_to_shared(xs);
    const unsigned sA_u = (unsigned)__cvta_generic_to_shared(sA);
    const unsigned sB_u = (unsigned)__cvta_generic_to_shared(sB);
    const unsigned sA_w = sA_u + (warp * 4) * CH * 4;   // this warp's 4 bin rows
    const unsigned sB_w = sB_u + (warp * 4) * CH * 4;

    const float4* gA4 = (const float4*)g_A;
    const float4* gB4 = (const float4*)g_B;

    for (int nc = 0; nc < FFTLEN; nc += CH) {
        __syncthreads();   // protects prev chunk reads (and x load at nc=0)
        for (int i4 = tid; i4 < KT * CH / 4; i4 += 224) {   // 896 float4 each
            const int kk = i4 >> 5;       // /(CH/4)
            const int c4 = i4 & 31;
            const int g  = (((kbase + kk) * FFTLEN + nc) >> 2) + c4;
            ((float4*)sA)[i4] = gA4[g];
            ((float4*)sB)[i4] = gB4[g];
        }
        __syncthreads();

        const int j  = nc >> 9;      // CH divides 512 -> j constant per chunk
        const int r0 = nc & 511;
        const unsigned x1u = xs_u + (unsigned)(((lane      + j) * RPAD + r0) * 4);
        const unsigned x2u = xs_u + (unsigned)(((lane + 32 + j) * RPAD + r0) * 4);

        #pragma unroll 4
        for (int c = 0; c < CH; c += 4) {
            ull x1a, x1b, x2a, x2b;
            LDSV2(x1a, x1b, x1u + c * 4);
            LDSV2(x2a, x2b, x2u + c * 4);
            #pragma unroll
            for (int q = 0; q < 4; q++) {
                ull Aa, Ab, Ba, Bb;
                LDSV2(Aa, Ab, sA_w + (q * CH + c) * 4);
                LDSV2(Ba, Bb, sB_w + (q * CH + c) * 4);
                aR0[q] = ffma2(Aa, x1a, aR0[q]);
                aR0[q] = ffma2(Ab, x1b, aR0[q]);
                aR1[q] = ffma2(Aa, x2a, aR1[q]);
                aR1[q] = ffma2(Ab, x2b, aR1[q]);
                aI0[q] = ffma2(Ba, x1a, aI0[q]);
                aI0[q] = ffma2(Bb, x1b, aI0[q]);
                aI1[q] = ffma2(Ba, x2a, aI1[q]);
                aI1[q] = ffma2(Bb, x2b, aI1[q]);
            }
        }
    }

    // ---- epilogue: fold pair-sums, magnitude, store ----
    const int f0 = bf * FT;
    #pragma unroll
    for (int q = 0; q < 4; q++) {
        const int k = kbase + warp * 4 + q;
        const float r0v = hsum2(aR0[q]);
        const float i0v = hsum2(aI0[q]);
        const float r1v = hsum2(aR1[q]);
        const float i1v = hsum2(aI1[q]);
        const int f1 = f0 + lane;
        const int f2 = f0 + lane + 32;
        if (f1 < NFRAMES) out[k * NFRAMES + f1] = sqrtf(r0v * r0v + i0v * i0v);
        if (f2 < NFRAMES) out[k * NFRAMES + f2] = sqrtf(r1v * r1v + i1v * i1v);
    }
}

extern "C" void kernel_launch(void* const* d_in, const int* in_sizes, int n_in,
                              void* d_out, int out_size) {
    const float* x    = (const float*)d_in[0];
    const float* wcos = (const float*)d_in[1];
    const float* wsin = (const float*)d_in[2];
    const float* kr   = (const float*)d_in[3];
    const float* ki   = (const float*)d_in[4];
    float* out = (float*)d_out;

    cudaFuncSetAttribute(cqt_main, cudaFuncAttributeMaxDynamicSharedMemorySize,
                         SMEM_BYTES);

    cqt_precomp<<<dim3(32, 7), 256>>>(wcos, wsin, kr, ki);

    const int fgrids = (NFRAMES + FT - 1) / FT;   // 256
    cqt_main<<<dim3(fgrids, 3), 224, SMEM_BYTES>>>(x, out);
}

// round 2
// speedup vs baseline: 1.1806x; 1.1806x over previous
#include <cuda_runtime.h>
#include <math.h>

#define T_SAMPLES 8388608
#define NFRAMES   16381
#define NBINS     84
#define FBINS     1025
#define FFTLEN    2048
#define HOP       512

// main kernel tiling
#define FT   64     // frames per block (32 lanes x 2 frames/thread)
#define KT   28     // bins per block (7 warps x 4 bins)
#define CH   128    // n-chunk staged in smem
#define XR   132    // x-chunk row stride (128 + 4 pad: %32==4 -> conflict-free LDS128)

#define SMEM_FLOATS (FT*XR + 2*KT*CH)
#define SMEM_BYTES  (SMEM_FLOATS * 4)

typedef unsigned long long ull;

// Combined CQT kernels: A = kr@wcos - ki@wsin, B = kr@wsin + ki@wcos
__device__ float g_A[NBINS * FFTLEN];
__device__ float g_B[NBINS * FFTLEN];

__device__ __forceinline__ ull ffma2(ull a, ull b, ull c) {
    ull d;
    asm("fma.rn.f32x2 %0, %1, %2, %3;" : "=l"(d) : "l"(a), "l"(b), "l"(c));
    return d;
}

__device__ __forceinline__ ull pack2(float lo, float hi) {
    ull r;
    asm("mov.b64 %0, {%1, %2};" : "=l"(r) : "f"(lo), "f"(hi));
    return r;
}

#define LDSV2(lo, hi, addr) \
    asm volatile("ld.shared.v2.u64 {%0, %1}, [%2];" : "=l"(lo), "=l"(hi) : "r"(addr))

__device__ __forceinline__ float hsum2(ull v) {
    union { ull u; float2 f; } c; c.u = v;
    return c.f.x + c.f.y;
}

// ---------------------------------------------------------------------------
// Precompute A,B [84,2048] = combine(kr,ki [84,1025] ; wcos,wsin [1025,2048])
// Packed f32x2: each thread owns one n-PAIR, 3 bins. Block = 4 k-slots x 64
// n-pairs (256 thr). kr/ki staged pre-splatted (incl. negated ki) in smem.
// Grid (16,7) = 112 blocks -> single balanced wave.
// ---------------------------------------------------------------------------
__global__ void __launch_bounds__(256) cqt_precomp(const float* __restrict__ wcos,
                                                   const float* __restrict__ wsin,
                                                   const float* __restrict__ kr,
                                                   const float* __restrict__ ki) {
    __shared__ ull s_r [12 * 64];   // {vr, vr}
    __shared__ ull s_in[12 * 64];   // {-vi,-vi}
    __shared__ ull s_ip[12 * 64];   // {vi, vi}
    const int tid = threadIdx.x;
    const int np  = blockIdx.x * 64 + (tid & 63);   // n-pair: n = 2*np, 2*np+1
    const int ks  = tid >> 6;                       // 0..3
    const int kb  = blockIdx.y * 12;                // 7 blocks -> 84 bins

    const ull* wc2 = (const ull*)wcos;
    const ull* ws2 = (const ull*)wsin;

    ull aA[3] = {0ULL, 0ULL, 0ULL};
    ull aB[3] = {0ULL, 0ULL, 0ULL};

    for (int bc = 0; bc < FBINS; bc += 64) {
        const int blen = min(64, FBINS - bc);
        __syncthreads();
        for (int i = tid; i < 12 * 64; i += 256) {
            const int kk = i >> 6, bb = i & 63;
            float vr = 0.f, vi = 0.f;
            if (bb < blen) {
                vr = kr[(kb + kk) * FBINS + bc + bb];
                vi = ki[(kb + kk) * FBINS + bc + bb];
            }
            s_r [i] = pack2(vr, vr);
            s_in[i] = pack2(-vi, -vi);
            s_ip[i] = pack2(vi, vi);
        }
        __syncthreads();
        #pragma unroll 4
        for (int bb = 0; bb < blen; bb++) {
            const int b = bc + bb;
            const ull wc = wc2[b * (FFTLEN / 2) + np];
            const ull ws = ws2[b * (FFTLEN / 2) + np];
            #pragma unroll
            for (int i = 0; i < 3; i++) {
                const int kk = (ks + 4 * i) * 64 + bb;
                const ull vr  = s_r [kk];
                const ull vin = s_in[kk];
                const ull vip = s_ip[kk];
                aA[i] = ffma2(vr,  wc, aA[i]);
                aA[i] = ffma2(vin, ws, aA[i]);
                aB[i] = ffma2(vr,  ws, aB[i]);
                aB[i] = ffma2(vip, wc, aB[i]);
            }
        }
    }
    #pragma unroll
    for (int i = 0; i < 3; i++) {
        const int k = kb + ks + 4 * i;
        ((ull*)g_A)[k * (FFTLEN / 2) + np] = aA[i];
        ((ull*)g_B)[k * (FFTLEN / 2) + np] = aB[i];
    }
}

// ---------------------------------------------------------------------------
// Main kernel: cqt[k,f] = sqrt((A[k]·frame_f)^2 + (B[k]·frame_f)^2)
// frame_f[n] = x[512*f + n]. Block = 28 bins x 64 frames, 224 threads.
// Per n-chunk of 128: stream x slice (64 frames x 128 samples) AND A/B chunk
// into smem, then packed-f32x2 rank-128 update. Smem ~62.5 KB -> 3 blocks/SM
// (21 warps) for latency hiding.
// ---------------------------------------------------------------------------
__global__ void __launch_bounds__(224, 3) cqt_main(const float* __restrict__ x,
                                                   float* __restrict__ out) {
    extern __shared__ float smem[];
    float* xs = smem;                 // FT * XR
    float* sA = smem + FT * XR;       // KT * CH
    float* sB = sA + KT * CH;

    const int tid   = threadIdx.x;
    const int lane  = tid & 31;
    const int warp  = tid >> 5;          // 0..6
    const int bf    = blockIdx.x;        // 0..255 frame tile
    const int bk    = blockIdx.y;        // 0..2 bin tile
    const int kbase = bk * KT;

    ull aR0[4], aR1[4], aI0[4], aI1[4];
    #pragma unroll
    for (int q = 0; q < 4; q++) { aR0[q] = aR1[q] = aI0[q] = aI1[q] = 0ULL; }

    const unsigned xs_u = (unsigned)__cvta_generic_to_shared(xs);
    const unsigned sA_u = (unsigned)__cvta_generic_to_shared(sA);
    const unsigned sB_u = (unsigned)__cvta_generic_to_shared(sB);
    const unsigned sA_w = sA_u + (warp * 4) * CH * 4;   // this warp's 4 bin rows
    const unsigned sB_w = sB_u + (warp * 4) * CH * 4;
    const unsigned x1u  = xs_u + (unsigned)((lane       * XR) * 4);
    const unsigned x2u  = xs_u + (unsigned)(((lane + 32) * XR) * 4);

    const float4* x4  = (const float4*)x;
    const float4* gA4 = (const float4*)g_A;
    const float4* gB4 = (const float4*)g_B;

    for (int nc = 0; nc < FFTLEN; nc += CH) {
        __syncthreads();   // protect prev chunk reads

        // stream x slice: frame f needs x[512*f + nc .. +127]
        const int xbase4 = bf * (FT * HOP / 4) + (nc >> 2);
        for (int i4 = tid; i4 < FT * (CH / 4); i4 += 224) {   // 2048 float4
            const int f  = i4 >> 5;
            const int c4 = i4 & 31;
            const int g4 = xbase4 + f * (HOP / 4) + c4;
            float4 v = make_float4(0.f, 0.f, 0.f, 0.f);
            if (g4 < T_SAMPLES / 4) v = x4[g4];
            *(float4*)(xs + f * XR + c4 * 4) = v;
        }
        // stage A/B chunk
        for (int i4 = tid; i4 < KT * CH / 4; i4 += 224) {     // 896 float4 each
            const int kk = i4 >> 5;
            const int c4 = i4 & 31;
            const int g  = (((kbase + kk) * FFTLEN + nc) >> 2) + c4;
            ((float4*)sA)[i4] = gA4[g];
            ((float4*)sB)[i4] = gB4[g];
        }
        __syncthreads();

        #pragma unroll 4
        for (int c = 0; c < CH; c += 4) {
            ull x1a, x1b, x2a, x2b;
            LDSV2(x1a, x1b, x1u + c * 4);
            LDSV2(x2a, x2b, x2u + c * 4);
            #pragma unroll
            for (int q = 0; q < 4; q++) {
                ull Aa, Ab, Ba, Bb;
                LDSV2(Aa, Ab, sA_w + (q * CH + c) * 4);
                LDSV2(Ba, Bb, sB_w + (q * CH + c) * 4);
                aR0[q] = ffma2(Aa, x1a, aR0[q]);
                aR0[q] = ffma2(Ab, x1b, aR0[q]);
                aR1[q] = ffma2(Aa, x2a, aR1[q]);
                aR1[q] = ffma2(Ab, x2b, aR1[q]);
                aI0[q] = ffma2(Ba, x1a, aI0[q]);
                aI0[q] = ffma2(Bb, x1b, aI0[q]);
                aI1[q] = ffma2(Ba, x2a, aI1[q]);
                aI1[q] = ffma2(Bb, x2b, aI1[q]);
            }
        }
    }

    // ---- epilogue: fold pair-sums, magnitude, store ----
    const int f0 = bf * FT;
    #pragma unroll
    for (int q = 0; q < 4; q++) {
        const int k = kbase + warp * 4 + q;
        const float r0v = hsum2(aR0[q]);
        const float i0v = hsum2(aI0[q]);
        const float r1v = hsum2(aR1[q]);
        const float i1v = hsum2(aI1[q]);
        const int f1 = f0 + lane;
        const int f2 = f0 + lane + 32;
        if (f1 < NFRAMES) out[k * NFRAMES + f1] = sqrtf(r0v * r0v + i0v * i0v);
        if (f2 < NFRAMES) out[k * NFRAMES + f2] = sqrtf(r1v * r1v + i1v * i1v);
    }
}

extern "C" void kernel_launch(void* const* d_in, const int* in_sizes, int n_in,
                              void* d_out, int out_size) {
    const float* x    = (const float*)d_in[0];
    const float* wcos = (const float*)d_in[1];
    const float* wsin = (const float*)d_in[2];
    const float* kr   = (const float*)d_in[3];
    const float* ki   = (const float*)d_in[4];
    float* out = (float*)d_out;

    cudaFuncSetAttribute(cqt_main, cudaFuncAttributeMaxDynamicSharedMemorySize,
                         SMEM_BYTES);

    cqt_precomp<<<dim3(16, 7), 256>>>(wcos, wsin, kr, ki);

    const int fgrids = (NFRAMES + FT - 1) / FT;   // 256
    cqt_main<<<dim3(fgrids, 3), 224, SMEM_BYTES>>>(x, out);
}

// round 5
// speedup vs baseline: 1.1903x; 1.0082x over previous
#include <cuda_runtime.h>
#include <math.h>

#define T_SAMPLES 8388608
#define NFRAMES   16381
#define NBINS     84
#define FBINS     1025
#define FFTLEN    2048
#define HOP       512

// main kernel tiling
#define FT   64     // frames per block (32 lanes x 2 frames/thread)
#define KT   28     // bins per block (7 warps x 4 bins)
#define CH   128    // n-chunk staged in smem
#define XR   132    // x-chunk row stride (128 + 4 pad: %32==4 -> conflict-free LDS128)

#define SMEM_FLOATS (FT*XR + 2*KT*CH)
#define SMEM_BYTES  (SMEM_FLOATS * 4)

typedef unsigned long long ull;

// Combined CQT kernels: A = kr@wcos - ki@wsin, B = kr@wsin + ki@wcos
__device__ float g_A[NBINS * FFTLEN];
__device__ float g_B[NBINS * FFTLEN];

__device__ __forceinline__ ull ffma2(ull a, ull b, ull c) {
    ull d;
    asm("fma.rn.f32x2 %0, %1, %2, %3;" : "=l"(d) : "l"(a), "l"(b), "l"(c));
    return d;
}

__device__ __forceinline__ ull pack2(float lo, float hi) {
    ull r;
    asm("mov.b64 %0, {%1, %2};" : "=l"(r) : "f"(lo), "f"(hi));
    return r;
}

#define LDSV2(lo, hi, addr) \
    asm volatile("ld.shared.v2.u64 {%0, %1}, [%2];" : "=l"(lo), "=l"(hi) : "r"(addr))

__device__ __forceinline__ float hsum2(ull v) {
    union { ull u; float2 f; } c; c.u = v;
    return c.f.x + c.f.y;
}

// ---------------------------------------------------------------------------
// Precompute A,B [84,2048] = combine(kr,ki [84,1025] ; wcos,wsin [1025,2048])
// Packed f32x2: each thread owns one n-PAIR, 3 bins. Block = 4 k-slots x 64
// n-pairs (256 thr). kr/ki staged pre-splatted (incl. negated ki) in smem.
// Grid (16,7) = 112 blocks -> single balanced wave.
// ---------------------------------------------------------------------------
__global__ void __launch_bounds__(256) cqt_precomp(const float* __restrict__ wcos,
                                                   const float* __restrict__ wsin,
                                                   const float* __restrict__ kr,
                                                   const float* __restrict__ ki) {
    __shared__ ull s_r [12 * 64];   // {vr, vr}
    __shared__ ull s_in[12 * 64];   // {-vi,-vi}
    __shared__ ull s_ip[12 * 64];   // {vi, vi}
    const int tid = threadIdx.x;
    const int np  = blockIdx.x * 64 + (tid & 63);   // n-pair: n = 2*np, 2*np+1
    const int ks  = tid >> 6;                       // 0..3
    const int kb  = blockIdx.y * 12;                // 7 blocks -> 84 bins

    const ull* wc2 = (const ull*)wcos;
    const ull* ws2 = (const ull*)wsin;

    ull aA[3] = {0ULL, 0ULL, 0ULL};
    ull aB[3] = {0ULL, 0ULL, 0ULL};

    for (int bc = 0; bc < FBINS; bc += 64) {
        const int blen = min(64, FBINS - bc);
        __syncthreads();
        for (int i = tid; i < 12 * 64; i += 256) {
            const int kk = i >> 6, bb = i & 63;
            float vr = 0.f, vi = 0.f;
            if (bb < blen) {
                vr = kr[(kb + kk) * FBINS + bc + bb];
                vi = ki[(kb + kk) * FBINS + bc + bb];
            }
            s_r [i] = pack2(vr, vr);
            s_in[i] = pack2(-vi, -vi);
            s_ip[i] = pack2(vi, vi);
        }
        __syncthreads();
        #pragma unroll 4
        for (int bb = 0; bb < blen; bb++) {
            const int b = bc + bb;
            const ull wc = wc2[b * (FFTLEN / 2) + np];
            const ull ws = ws2[b * (FFTLEN / 2) + np];
            #pragma unroll
            for (int i = 0; i < 3; i++) {
                const int kk = (ks + 4 * i) * 64 + bb;
                const ull vr  = s_r [kk];
                const ull vin = s_in[kk];
                const ull vip = s_ip[kk];
                aA[i] = ffma2(vr,  wc, aA[i]);
                aA[i] = ffma2(vin, ws, aA[i]);
                aB[i] = ffma2(vr,  ws, aB[i]);
                aB[i] = ffma2(vip, wc, aB[i]);
            }
        }
    }
    #pragma unroll
    for (int i = 0; i < 3; i++) {
        const int k = kb + ks + 4 * i;
        ((ull*)g_A)[k * (FFTLEN / 2) + np] = aA[i];
        ((ull*)g_B)[k * (FFTLEN / 2) + np] = aB[i];
    }
}

// ---------------------------------------------------------------------------
// Main kernel: cqt[k,f] = sqrt((A[k]·frame_f)^2 + (B[k]·frame_f)^2)
// frame_f[n] = x[512*f + n]. Block = 28 bins x 64 frames, 224 threads.
// Per n-chunk of 128: stream x slice (64 frames x 128 samples) AND A/B chunk
// into smem, then packed-f32x2 rank-128 update. Smem ~62.5 KB -> 3 blocks/SM
// (21 warps) for latency hiding.
// ---------------------------------------------------------------------------
__global__ void __launch_bounds__(224, 3) cqt_main(const float* __restrict__ x,
                                                   float* __restrict__ out) {
    extern __shared__ float smem[];
    float* xs = smem;                 // FT * XR
    float* sA = smem + FT * XR;       // KT * CH
    float* sB = sA + KT * CH;

    const int tid   = threadIdx.x;
    const int lane  = tid & 31;
    const int warp  = tid >> 5;          // 0..6
    const int bf    = blockIdx.x;        // 0..255 frame tile
    const int bk    = blockIdx.y;        // 0..2 bin tile
    const int kbase = bk * KT;

    ull aR0[4], aR1[4], aI0[4], aI1[4];
    #pragma unroll
    for (int q = 0; q < 4; q++) { aR0[q] = aR1[q] = aI0[q] = aI1[q] = 0ULL; }

    const unsigned xs_u = (unsigned)__cvta_generic_to_shared(xs);
    const unsigned sA_u = (unsigned)__cvta_generic_to_shared(sA);
    const unsigned sB_u = (unsigned)__cvta_generic_to_shared(sB);
    const unsigned sA_w = sA_u + (warp * 4) * CH * 4;   // this warp's 4 bin rows
    const unsigned sB_w = sB_u + (warp * 4) * CH * 4;
    const unsigned x1u  = xs_u + (unsigned)((lane       * XR) * 4);
    const unsigned x2u  = xs_u + (unsigned)(((lane + 32) * XR) * 4);

    const float4* x4  = (const float4*)x;
    const float4* gA4 = (const float4*)g_A;
    const float4* gB4 = (const float4*)g_B;

    for (int nc = 0; nc < FFTLEN; nc += CH) {
        __syncthreads();   // protect prev chunk reads

        // stream x slice: frame f needs x[512*f + nc .. +127]
        const int xbase4 = bf * (FT * HOP / 4) + (nc >> 2);
        for (int i4 = tid; i4 < FT * (CH / 4); i4 += 224) {   // 2048 float4
            const int f  = i4 >> 5;
            const int c4 = i4 & 31;
            const int g4 = xbase4 + f * (HOP / 4) + c4;
            float4 v = make_float4(0.f, 0.f, 0.f, 0.f);
            if (g4 < T_SAMPLES / 4) v = x4[g4];
            *(float4*)(xs + f * XR + c4 * 4) = v;
        }
        // stage A/B chunk
        for (int i4 = tid; i4 < KT * CH / 4; i4 += 224) {     // 896 float4 each
            const int kk = i4 >> 5;
            const int c4 = i4 & 31;
            const int g  = (((kbase + kk) * FFTLEN + nc) >> 2) + c4;
            ((float4*)sA)[i4] = gA4[g];
            ((float4*)sB)[i4] = gB4[g];
        }
        __syncthreads();

        #pragma unroll 4
        for (int c = 0; c < CH; c += 4) {
            ull x1a, x1b, x2a, x2b;
            LDSV2(x1a, x1b, x1u + c * 4);
            LDSV2(x2a, x2b, x2u + c * 4);
            #pragma unroll
            for (int q = 0; q < 4; q++) {
                ull Aa, Ab, Ba, Bb;
                LDSV2(Aa, Ab, sA_w + (q * CH + c) * 4);
                LDSV2(Ba, Bb, sB_w + (q * CH + c) * 4);
                aR0[q] = ffma2(Aa, x1a, aR0[q]);
                aR0[q] = ffma2(Ab, x1b, aR0[q]);
                aR1[q] = ffma2(Aa, x2a, aR1[q]);
                aR1[q] = ffma2(Ab, x2b, aR1[q]);
                aI0[q] = ffma2(Ba, x1a, aI0[q]);
                aI0[q] = ffma2(Bb, x1b, aI0[q]);
                aI1[q] = ffma2(Ba, x2a, aI1[q]);
                aI1[q] = ffma2(Bb, x2b, aI1[q]);
            }
        }
    }

    // ---- epilogue: fold pair-sums, magnitude, store ----
    const int f0 = bf * FT;
    #pragma unroll
    for (int q = 0; q < 4; q++) {
        const int k = kbase + warp * 4 + q;
        const float r0v = hsum2(aR0[q]);
        const float i0v = hsum2(aI0[q]);
        const float r1v = hsum2(aR1[q]);
        const float i1v = hsum2(aI1[q]);
        const int f1 = f0 + lane;
        const int f2 = f0 + lane + 32;
        if (f1 < NFRAMES) out[k * NFRAMES + f1] = sqrtf(r0v * r0v + i0v * i0v);
        if (f2 < NFRAMES) out[k * NFRAMES + f2] = sqrtf(r1v * r1v + i1v * i1v);
    }
}

extern "C" void kernel_launch(void* const* d_in, const int* in_sizes, int n_in,
                              void* d_out, int out_size) {
    const float* x    = (const float*)d_in[0];
    const float* wcos = (const float*)d_in[1];
    const float* wsin = (const float*)d_in[2];
    const float* kr   = (const float*)d_in[3];
    const float* ki   = (const float*)d_in[4];
    float* out = (float*)d_out;

    cudaFuncSetAttribute(cqt_main, cudaFuncAttributeMaxDynamicSharedMemorySize,
                         SMEM_BYTES);

    cqt_precomp<<<dim3(16, 7), 256>>>(wcos, wsin, kr, ki);

    const int fgrids = (NFRAMES + FT - 1) / FT;   // 256
    cqt_main<<<dim3(fgrids, 3), 224, SMEM_BYTES>>>(x, out);
}